// round 12
// baseline (speedup 1.0000x reference)
#include <cuda_runtime.h>
#include <cuda_fp16.h>
#include <cstdint>

#define NF     39
#define BATCH  8192
#define PAIRS  4096
#define NTH    512
#define GRID   296                      // 148 SMs x 2 CTAs = one full wave
#define MAXP   14                       // max pairs per CTA

#define SA     112                      // row stride bytes (48 fp16 + pad)
#define SAH    56

#define WSCALE 128.0f
#define INV_P  (1.0f/16384.0f)
#define INV_T  (1.0f/2097152.0f)

// dynamic smem offsets (bytes)
#define O_IDX  0                        // int [2][80]
#define O_LIN  640                      // float [MAXP][80]
#define O_PB   5120                     // float [MAXP][16][32]
#define O_A    33792                    // u16 [2][128*SAH]
#define O_B    62464                    // u16 [160*SAH]
#define SMEM_TOTAL 80384

static __device__ __forceinline__ uint32_t s2u(const void* p){
    uint32_t a;
    asm("{ .reg .u64 t; cvta.to.shared.u64 t, %1; cvt.u32.u64 %0, t; }" : "=r"(a) : "l"(p));
    return a;
}
static __device__ __forceinline__ uint32_t pack_h2(float a, float b){
    __half2 h = __float22half2_rn(make_float2(a, b));
    return *(uint32_t*)&h;
}

#define LDSM4(r, a) \
    asm volatile("ldmatrix.sync.aligned.m8n8.x4.shared.b16 {%0,%1,%2,%3}, [%4];" \
        : "=r"((r)[0]),"=r"((r)[1]),"=r"((r)[2]),"=r"((r)[3]) : "r"(a))
#define LDSM2(r, a) \
    asm volatile("ldmatrix.sync.aligned.m8n8.x2.shared.b16 {%0,%1}, [%2];" \
        : "=r"((r)[0]),"=r"((r)[1]) : "r"(a))
#define MMAH(d, a, b0, b1) \
    asm volatile("mma.sync.aligned.m16n8k16.row.col.f16.f16.f16.f16 " \
        "{%0,%1},{%2,%3,%4,%5},{%6,%7},{%0,%1};" \
        : "+r"((d)[0]),"+r"((d)[1]) \
        : "r"((a)[0]),"r"((a)[1]),"r"((a)[2]),"r"((a)[3]), "r"(b0),"r"(b1))

__global__ __launch_bounds__(NTH, 2)
void tfm_mma_kernel(const int*   __restrict__ x,
                    const float* __restrict__ table,
                    const float* __restrict__ lw,
                    const float* __restrict__ lb,
                    const float* __restrict__ W0,
                    const float* __restrict__ W1,
                    float*       __restrict__ out)
{
    extern __shared__ char sm[];
    int*      idxr = (int*)(sm + O_IDX);        // [slot*80 + row*39 + k]
    float*    linA = (float*)(sm + O_LIN);      // [pair*80 + row*39 + k]
    float*    Pb   = (float*)(sm + O_PB);       // [pair*512 + wid*32 + lid]
    uint16_t* Ab   = (uint16_t*)(sm + O_A);
    uint16_t* Bb   = (uint16_t*)(sm + O_B);

    const int tid = threadIdx.x;
    const int wid = tid >> 5;
    const int lid = tid & 31;
    const int bid = blockIdx.x;
    const int np  = (PAIRS - bid + GRID - 1) / GRID;     // 13 or 14

    // ---- zero A slots + B (covers K pads) ----
    for (int t = tid; t < (2*128*SA + 160*SA) / 16; t += NTH)
        ((float4*)(sm + O_A))[t] = make_float4(0.f, 0.f, 0.f, 0.f);

    // ---- stage pair 0 ----
    if (tid < 2 * NF) {
        int row = tid / NF, k = tid % NF;
        int xi = x[(2 * bid + row) * NF + k];
        idxr[row * NF + k] = xi;
        linA[row * NF + k] = lw[xi];
    }
    __syncthreads();

    // ---- build B once: row n = s*32 + j, fp16, scaled ----
    for (int t = tid; t < 160 * NF; t += NTH) {
        int n = t / NF, k = t - n * NF;
        int s = n >> 5, j = n & 31;
        float w = (s < 2) ? W0[(s * 32 + j) * NF + k]
                          : W1[((s - 2) * 32 + j) * NF + k];
        Bb[n * SAH + k] = __half_as_ushort(__float2half_rn(w * WSCALE));
    }

    // A-build mapping: ar = row 0..127, kg = quarter of K
    const int ar = tid & 127;
    const int bh = ar >> 6;
    const int ai = ar & 63;
    const int kg = tid >> 7;            // 0..3
    const int k0 = kg * 10;             // in halves
    const int kn = (kg == 3) ? 9 : 10;

    // ---- build A pair 0 into slot 0 ----
    {
        uint32_t* ap = (uint32_t*)&Ab[ar * SAH + k0];
        #pragma unroll
        for (int p = 0; p < 5; p++) {
            int ka = k0 + 2*p, kb = ka + 1;
            float ea = (2*p     < kn) ? __ldg(table + (size_t)idxr[bh*NF + ka] * 64 + ai) : 0.f;
            float eb = (2*p + 1 < kn) ? __ldg(table + (size_t)idxr[bh*NF + kb] * 64 + ai) : 0.f;
            ap[p] = pack_h2(ea, eb);
        }
    }
    // ---- stage pair 1 into slot 1 ----
    if (np > 1 && tid < 2 * NF) {
        int row = tid / NF, k = tid % NF;
        int xi = x[(2 * (bid + GRID) + row) * NF + k];
        idxr[80 + row * NF + k] = xi;
        linA[80 + row * NF + k] = lw[xi];
    }
    __syncthreads();

    // warp tiling: wm = batch half, mq = embed half, wj = rank octet
    const int wm = wid & 1;
    const int mq = (wid >> 1) & 1;
    const int wj = wid >> 2;
    const uint32_t aOff  = (uint32_t)(wm*64 + mq*32 + (lid & 15)) * SA + (uint32_t)(lid >> 4) * 16u;
    const uint32_t aB0   = s2u(Ab) + aOff;
    const uint32_t aB1   = aB0 + 128u * SA;
    const uint32_t bBase = s2u(Bb) + (uint32_t)(wj*8 + (lid & 7)) * SA + (uint32_t)((lid >> 3) & 1) * 16u;

    for (int i = 0; i < np; i++) {
        const uint32_t aBase = (i & 1) ? aB1 : aB0;

        // ---- prefetch pair i+1 gathers (overlaps MMA) ----
        uint32_t pk[5];
        if (i + 1 < np) {
            const int* ib = idxr + ((i + 1) & 1) * 80 + bh * NF;
            #pragma unroll
            for (int p = 0; p < 5; p++) {
                int ka = k0 + 2*p, kb = ka + 1;
                float ea = (2*p     < kn) ? __ldg(table + (size_t)ib[ka] * 64 + ai) : 0.f;
                float eb = (2*p + 1 < kn) ? __ldg(table + (size_t)ib[kb] * 64 + ai) : 0.f;
                pk[p] = pack_h2(ea, eb);
            }
        }

        // ---- MMA: 5 segments x 2 m-tiles x 3 k-steps, f16 acc ----
        uint32_t acc[5][2][2];
        #pragma unroll
        for (int s = 0; s < 5; s++)
            #pragma unroll
            for (int mt = 0; mt < 2; mt++)
                acc[s][mt][0] = acc[s][mt][1] = 0u;

        #pragma unroll
        for (int ks = 0; ks < 3; ks++) {
            uint32_t af[2][4];
            LDSM4(af[0], aBase + (uint32_t)ks * 32u);
            LDSM4(af[1], aBase + 16u*SA + (uint32_t)ks * 32u);
            #pragma unroll
            for (int s = 0; s < 5; s++) {
                uint32_t bf[2];
                LDSM2(bf, bBase + (uint32_t)s * (32u*SA) + (uint32_t)ks * 32u);
                MMAH(acc[s][0], af[0], bf[0], bf[1]);
                MMAH(acc[s][1], af[1], bf[0], bf[1]);
            }
        }

        // ---- stage pair i+2 (slot i&1 free after prefetch above) ----
        if (i + 2 < np && tid < 2 * NF) {
            int row = tid / NF, k = tid % NF;
            int xi = x[(2 * (bid + (i + 2) * GRID) + row) * NF + k];
            idxr[(i & 1) * 80 + row * NF + k] = xi;
            linA[(i + 2) * 80 + row * NF + k] = lw[xi];
        }

        // ---- store prefetched A into other slot ----
        if (i + 1 < np) {
            uint32_t* ap = (uint32_t*)&Ab[((i + 1) & 1) * 128 * SAH + ar * SAH + k0];
            #pragma unroll
            for (int p = 0; p < 5; p++) ap[p] = pk[p];
        }

        // ---- half2 epilogue, one STS ----
        {
            __half2 pair2 = __float2half2_rn(0.f);
            __half2 trip2 = __float2half2_rn(0.f);
            #pragma unroll
            for (int mt = 0; mt < 2; mt++)
                #pragma unroll
                for (int r = 0; r < 2; r++) {
                    __half2 d0 = *(const __half2*)&acc[0][mt][r];
                    __half2 d1 = *(const __half2*)&acc[1][mt][r];
                    __half2 d2 = *(const __half2*)&acc[2][mt][r];
                    __half2 d3 = *(const __half2*)&acc[3][mt][r];
                    __half2 d4 = *(const __half2*)&acc[4][mt][r];
                    pair2 = __hfma2(d0, d1, pair2);
                    trip2 = __hfma2(__hmul2(d2, d3), d4, trip2);
                }
            float2 pp = __half22float2(pair2);
            float2 qq = __half22float2(trip2);
            Pb[i * 512 + wid * 32 + lid] =
                (pp.x + pp.y) * INV_P + (qq.x + qq.y) * INV_T;
        }

        __syncthreads();   // A[alt] + idxr + Pb visible
    }

    // ---- final: one warp per output (pair, row) ----
    for (int o = wid; o < 2 * np; o += 16) {
        int pair = o >> 1, r = o & 1;
        const float* pb = Pb + pair * 512;
        float s = 0.f;
        #pragma unroll
        for (int w = 0; w < 8; w++)                 // warps with wm == r
            s += pb[(r + 2 * w) * 32 + lid];
        s += linA[pair * 80 + r * NF + lid];
        if (lid < NF - 32) s += linA[pair * 80 + r * NF + 32 + lid];
        #pragma unroll
        for (int off = 16; off > 0; off >>= 1)
            s += __shfl_down_sync(0xffffffffu, s, off);
        if (lid == 0) out[2 * (bid + pair * GRID) + r] = s + lb[0];
    }
}

extern "C" void kernel_launch(void* const* d_in, const int* in_sizes, int n_in,
                              void* d_out, int out_size)
{
    const int*   x     = (const int*)  d_in[0];
    const float* table = (const float*)d_in[1];
    const float* lw    = (const float*)d_in[2];
    const float* lb    = (const float*)d_in[3];
    const float* W0    = (const float*)d_in[4];
    const float* W1    = (const float*)d_in[5];
    float*       out   = (float*)d_out;
    (void)in_sizes; (void)n_in; (void)out_size;

    cudaFuncSetAttribute(tfm_mma_kernel, cudaFuncAttributeMaxDynamicSharedMemorySize, SMEM_TOTAL);
    tfm_mma_kernel<<<GRID, NTH, SMEM_TOTAL>>>(x, table, lw, lb, W0, W1, out);
}

// round 13
// speedup vs baseline: 1.2053x; 1.2053x over previous
#include <cuda_runtime.h>
#include <cuda_fp16.h>
#include <cstdint>

#define NF     39
#define BATCH  8192
#define PAIRS  4096
#define NTH    256
#define GRID   296                      // 148 SMs x 2 CTAs = one full wave
#define MAXP   14                       // max pairs per CTA

#define SA     112                      // row stride bytes (48 fp16 + pad)
#define SAH    56

#define WSCALE 128.0f
#define INV_P  (1.0f/16384.0f)
#define INV_T  (1.0f/2097152.0f)

// dynamic smem offsets (bytes)
#define O_IDX  0                        // int [2][80]
#define O_LIN  640                      // float [MAXP][80]
#define O_PB   5120                     // float [MAXP][8][32]
#define O_A    19456                    // u16 [2][128*SAH]
#define O_B    48128                    // u16 [160*SAH]
#define SMEM_TOTAL 66048

static __device__ __forceinline__ uint32_t s2u(const void* p){
    uint32_t a;
    asm("{ .reg .u64 t; cvta.to.shared.u64 t, %1; cvt.u32.u64 %0, t; }" : "=r"(a) : "l"(p));
    return a;
}
static __device__ __forceinline__ uint32_t pack_h2(float a, float b){
    __half2 h = __float22half2_rn(make_float2(a, b));
    return *(uint32_t*)&h;
}

#define LDSM4(r, a) \
    asm volatile("ldmatrix.sync.aligned.m8n8.x4.shared.b16 {%0,%1,%2,%3}, [%4];" \
        : "=r"((r)[0]),"=r"((r)[1]),"=r"((r)[2]),"=r"((r)[3]) : "r"(a))
#define LDSM2(r, a) \
    asm volatile("ldmatrix.sync.aligned.m8n8.x2.shared.b16 {%0,%1}, [%2];" \
        : "=r"((r)[0]),"=r"((r)[1]) : "r"(a))
#define MMAH(d, a, b0, b1) \
    asm volatile("mma.sync.aligned.m16n8k16.row.col.f16.f16.f16.f16 " \
        "{%0,%1},{%2,%3,%4,%5},{%6,%7},{%0,%1};" \
        : "+r"((d)[0]),"+r"((d)[1]) \
        : "r"((a)[0]),"r"((a)[1]),"r"((a)[2]),"r"((a)[3]), "r"(b0),"r"(b1))

__global__ __launch_bounds__(NTH, 2)
void tfm_mma_kernel(const int*   __restrict__ x,
                    const float* __restrict__ table,
                    const float* __restrict__ lw,
                    const float* __restrict__ lb,
                    const float* __restrict__ W0,
                    const float* __restrict__ W1,
                    float*       __restrict__ out)
{
    extern __shared__ char sm[];
    int*      idxr = (int*)(sm + O_IDX);        // [slot*80 + row*39 + k]
    float*    linA = (float*)(sm + O_LIN);      // [pair*80 + row*39 + k]
    float*    Pb   = (float*)(sm + O_PB);       // [pair*256 + wid*32 + lid]
    uint16_t* Ab   = (uint16_t*)(sm + O_A);
    uint16_t* Bb   = (uint16_t*)(sm + O_B);

    const int tid = threadIdx.x;
    const int wid = tid >> 5;
    const int lid = tid & 31;
    const int bid = blockIdx.x;
    const int np  = (PAIRS - bid + GRID - 1) / GRID;     // 13 or 14

    // ---- zero A slots + B (covers K pads) ----
    for (int t = tid; t < (2*128*SA + 160*SA) / 16; t += NTH)
        ((float4*)(sm + O_A))[t] = make_float4(0.f, 0.f, 0.f, 0.f);

    // ---- stage pair 0 ----
    if (tid < 2 * NF) {
        int row = tid / NF, k = tid % NF;
        int xi = x[(2 * bid + row) * NF + k];
        idxr[row * NF + k] = xi;
        linA[row * NF + k] = lw[xi];
    }
    __syncthreads();

    // ---- build B once: row n = s*32 + j, fp16, scaled ----
    for (int t = tid; t < 160 * NF; t += NTH) {
        int n = t / NF, k = t - n * NF;
        int s = n >> 5, j = n & 31;
        float w = (s < 2) ? W0[(s * 32 + j) * NF + k]
                          : W1[((s - 2) * 32 + j) * NF + k];
        Bb[n * SAH + k] = __half_as_ushort(__float2half_rn(w * WSCALE));
    }

    // A-build mapping: ar = row 0..127 (bh*64 + embed), kg = k-half
    const int ar = tid & 127;
    const int bh = ar >> 6;
    const int ai = ar & 63;
    const int kg = tid >> 7;
    const int k0 = kg * 20;
    const int kn = kg ? 19 : 20;

    // ---- build A pair 0 into slot 0 ----
    {
        uint32_t* ap = (uint32_t*)&Ab[ar * SAH + k0];
        #pragma unroll
        for (int p = 0; p < 10; p++) {
            int ka = k0 + 2*p, kb = ka + 1;
            float ea = (2*p     < kn) ? __ldg(table + (size_t)idxr[bh*NF + ka] * 64 + ai) : 0.f;
            float eb = (2*p + 1 < kn) ? __ldg(table + (size_t)idxr[bh*NF + kb] * 64 + ai) : 0.f;
            ap[p] = pack_h2(ea, eb);
        }
    }
    // ---- stage pair 1 into slot 1 ----
    if (np > 1 && tid < 2 * NF) {
        int row = tid / NF, k = tid % NF;
        int xi = x[(2 * (bid + GRID) + row) * NF + k];
        idxr[80 + row * NF + k] = xi;
        linA[80 + row * NF + k] = lw[xi];
    }
    __syncthreads();

    // warp tiling: wm = batch half, wj = rank octet
    const int wm = wid & 1;
    const int wj = wid >> 1;
    const uint32_t aOff  = (uint32_t)(wm*64 + (lid & 15)) * SA + (uint32_t)(lid >> 4) * 16u;
    const uint32_t aB0   = s2u(Ab) + aOff;
    const uint32_t aB1   = aB0 + 128u * SA;
    const uint32_t bBase = s2u(Bb) + (uint32_t)(wj*8 + (lid & 7)) * SA + (uint32_t)((lid >> 3) & 1) * 16u;

    // ---- hoist ALL B fragments into registers (constant across pairs) ----
    uint32_t bfr[3][5][2];
    #pragma unroll
    for (int ks = 0; ks < 3; ks++)
        #pragma unroll
        for (int s = 0; s < 5; s++)
            LDSM2(bfr[ks][s], bBase + (uint32_t)s * (32u*SA) + (uint32_t)ks * 32u);

    for (int i = 0; i < np; i++) {
        const uint32_t aBase = (i & 1) ? aB1 : aB0;

        // ---- prefetch pair i+1 gathers (overlaps MMA) ----
        uint32_t pk[10];
        if (i + 1 < np) {
            const int* ib = idxr + ((i + 1) & 1) * 80 + bh * NF;
            #pragma unroll
            for (int p = 0; p < 10; p++) {
                int ka = k0 + 2*p, kb = ka + 1;
                float ea = (2*p     < kn) ? __ldg(table + (size_t)ib[ka] * 64 + ai) : 0.f;
                float eb = (2*p + 1 < kn) ? __ldg(table + (size_t)ib[kb] * 64 + ai) : 0.f;
                pk[p] = pack_h2(ea, eb);
            }
        }

        // ---- MMA: 5 segments x 4 m-tiles x 3 k-steps, f16 acc, B in regs ----
        uint32_t acc[5][4][2];
        #pragma unroll
        for (int s = 0; s < 5; s++)
            #pragma unroll
            for (int mt = 0; mt < 4; mt++)
                acc[s][mt][0] = acc[s][mt][1] = 0u;

        #pragma unroll
        for (int ks = 0; ks < 3; ks++) {
            #pragma unroll
            for (int mt = 0; mt < 4; mt++) {
                uint32_t af[4];
                LDSM4(af, aBase + (uint32_t)mt * (16u*SA) + (uint32_t)ks * 32u);
                #pragma unroll
                for (int s = 0; s < 5; s++)
                    MMAH(acc[s][mt], af, bfr[ks][s][0], bfr[ks][s][1]);
            }
        }

        // ---- stage pair i+2 (slot i&1 free after prefetch above) ----
        if (i + 2 < np && tid < 2 * NF) {
            int row = tid / NF, k = tid % NF;
            int xi = x[(2 * (bid + (i + 2) * GRID) + row) * NF + k];
            idxr[(i & 1) * 80 + row * NF + k] = xi;
            linA[(i + 2) * 80 + row * NF + k] = lw[xi];
        }

        // ---- store prefetched A into other slot ----
        if (i + 1 < np) {
            uint32_t* ap = (uint32_t*)&Ab[((i + 1) & 1) * 128 * SAH + ar * SAH + k0];
            #pragma unroll
            for (int p = 0; p < 10; p++) ap[p] = pk[p];
        }

        // ---- half2 epilogue, one STS ----
        {
            __half2 pair2 = __float2half2_rn(0.f);
            __half2 trip2 = __float2half2_rn(0.f);
            #pragma unroll
            for (int mt = 0; mt < 4; mt++)
                #pragma unroll
                for (int r = 0; r < 2; r++) {
                    __half2 d0 = *(const __half2*)&acc[0][mt][r];
                    __half2 d1 = *(const __half2*)&acc[1][mt][r];
                    __half2 d2 = *(const __half2*)&acc[2][mt][r];
                    __half2 d3 = *(const __half2*)&acc[3][mt][r];
                    __half2 d4 = *(const __half2*)&acc[4][mt][r];
                    pair2 = __hfma2(d0, d1, pair2);
                    trip2 = __hfma2(__hmul2(d2, d3), d4, trip2);
                }
            float2 pp = __half22float2(pair2);
            float2 qq = __half22float2(trip2);
            Pb[i * 256 + wid * 32 + lid] =
                (pp.x + pp.y) * INV_P + (qq.x + qq.y) * INV_T;
        }

        __syncthreads();   // A[alt] + idxr + Pb visible
    }

    // ---- final: one warp per output (pair, row) ----
    for (int o = wid; o < 2 * np; o += 8) {
        int pair = o >> 1, r = o & 1;
        const float* pb = Pb + pair * 256;
        float s = pb[(r    ) * 32 + lid] + pb[(r + 2) * 32 + lid]
                + pb[(r + 4) * 32 + lid] + pb[(r + 6) * 32 + lid];
        s += linA[pair * 80 + r * NF + lid];
        if (lid < NF - 32) s += linA[pair * 80 + r * NF + 32 + lid];
        #pragma unroll
        for (int off = 16; off > 0; off >>= 1)
            s += __shfl_down_sync(0xffffffffu, s, off);
        if (lid == 0) out[2 * (bid + pair * GRID) + r] = s + lb[0];
    }
}

extern "C" void kernel_launch(void* const* d_in, const int* in_sizes, int n_in,
                              void* d_out, int out_size)
{
    const int*   x     = (const int*)  d_in[0];
    const float* table = (const float*)d_in[1];
    const float* lw    = (const float*)d_in[2];
    const float* lb    = (const float*)d_in[3];
    const float* W0    = (const float*)d_in[4];
    const float* W1    = (const float*)d_in[5];
    float*       out   = (float*)d_out;
    (void)in_sizes; (void)n_in; (void)out_size;

    cudaFuncSetAttribute(tfm_mma_kernel, cudaFuncAttributeMaxDynamicSharedMemorySize, SMEM_TOTAL);
    tfm_mma_kernel<<<GRID, NTH, SMEM_TOTAL>>>(x, table, lw, lb, W0, W1, out);
}